// round 13
// baseline (speedup 1.0000x reference)
#include <cuda_runtime.h>
#include <cuda_fp16.h>
#include <cstdint>

#define NN 50000
#define EE 800000
#define GG 100
#define HH 128
#define FF 128
#define NGAUSS 50
#define NLAYER 6
#define NTILES (EE / 128)   // 6250
#define EGRID 148

typedef unsigned long long u64;
typedef unsigned int u32;

// ---------------- scratch (static device globals; no allocation) ----------------
__device__ float g_dist[EE];
__device__ float g_C[EE];
__device__ int   g_cnt[NN];     // re-zeroed by k_scan_xl each run
__device__ int   g_cur[NN];
__device__ float g_sd[EE];
__device__ float g_sc[EE];
__device__ int   g_ss[EE];
__device__ int   g_sdt[EE];
__device__ float g_h[(size_t)NN * HH];
__device__ float g_xl[(size_t)NN * FF];
__device__ float g_agg[(size_t)NN * FF];
// weights, fp16, [n][k] layout
__device__ __half g_w1t[NLAYER * 128 * 64];
__device__ __half g_w2t[NLAYER * 128 * 128];
__device__ __half g_cw2t[NLAYER * 128 * 128];
__device__ __half g_iwt[NLAYER * 128 * 128];
__device__ __half g_cw1t[NLAYER * 128 * 128];

// ---------------- generic helpers ----------------
__device__ __forceinline__ u64 pk2(float x, float y) {
    u64 r; asm("mov.b64 %0, {%1,%2};" : "=l"(r) : "f"(x), "f"(y)); return r;
}
__device__ __forceinline__ void fma2(u64& d, u64 a, u64 b) {
    asm("fma.rn.f32x2 %0, %1, %2, %0;" : "+l"(d) : "l"(a), "l"(b));
}
__device__ __forceinline__ float2 up2(u64 v) {
    float2 r; asm("mov.b64 {%0,%1}, %2;" : "=f"(r.x), "=f"(r.y) : "l"(v)); return r;
}
__device__ __forceinline__ void red4(float* p, float a, float b, float c, float d) {
    asm volatile("red.global.add.v4.f32 [%0], {%1,%2,%3,%4};"
                 :: "l"(p), "f"(a), "f"(b), "f"(c), "f"(d) : "memory");
}
__device__ __forceinline__ float ssp(float x) {
    return fmaxf(x, 0.0f) + __logf(1.0f + __expf(-fabsf(x))) - 0.69314718055994530942f;
}
__device__ __forceinline__ u32 smem_u32(const void* p) {
    u32 a; asm("{ .reg .u64 t; cvta.to.shared.u64 t, %1; cvt.u32.u64 %0, t; }" : "=r"(a) : "l"(p));
    return a;
}
__device__ __forceinline__ u32 pkh2(float x, float y) {
    __half2 t = __floats2half2_rn(x, y); return *(u32*)&t;
}

// ---------------- mma.sync fp16 helpers ----------------
__device__ __forceinline__ void ldmx4(u32* r, u32 addr) {
    asm volatile("ldmatrix.sync.aligned.m8n8.x4.shared.b16 {%0,%1,%2,%3}, [%4];"
                 : "=r"(r[0]), "=r"(r[1]), "=r"(r[2]), "=r"(r[3]) : "r"(addr));
}
__device__ __forceinline__ void mma16816(float* c, const u32* a, const u32* b) {
    asm volatile("mma.sync.aligned.m16n8k16.row.col.f32.f16.f16.f32 "
                 "{%0,%1,%2,%3}, {%4,%5,%6,%7}, {%8,%9}, {%0,%1,%2,%3};"
                 : "+f"(c[0]), "+f"(c[1]), "+f"(c[2]), "+f"(c[3])
                 : "r"(a[0]), "r"(a[1]), "r"(a[2]), "r"(a[3]), "r"(b[0]), "r"(b[1]));
}

#define ZACC4(acc) do { \
    _Pragma("unroll") for (int _m = 0; _m < 2; _m++) \
    _Pragma("unroll") for (int _n = 0; _n < 4; _n++) \
    _Pragma("unroll") for (int _q = 0; _q < 4; _q++) acc[_m][_n][_q] = 0.0f; } while (0)

// single-pass fp16 GEMM, warp tile 32x32 (2 m-frags x 2 n-frags)
template<int KS, int STRIDE>
__device__ __forceinline__ void gemm_1p(float acc[2][4][4], u32 Ab, u32 Bb) {
#pragma unroll
    for (int ks = 0; ks < KS; ks++) {
        u32 ah[2][4], bh[2][4];
        ldmx4(ah[0], Ab + ks * 32);
        ldmx4(ah[1], Ab + 16 * STRIDE + ks * 32);
        ldmx4(bh[0], Bb + ks * 32);
        ldmx4(bh[1], Bb + 16 * STRIDE + ks * 32);
#pragma unroll
        for (int mi = 0; mi < 2; mi++)
#pragma unroll
            for (int nb = 0; nb < 2; nb++) {
                mma16816(acc[mi][2*nb],   ah[mi], &bh[nb][0]);
                mma16816(acc[mi][2*nb+1], ah[mi], &bh[nb][2]);
            }
    }
}

// epilogue: ssp(acc + bias) -> fp16 into 272B-stride A buffer (own 32x32 subtile)
__device__ __forceinline__ void epi_ssp_h(const float acc[2][4][4],
        const float* bias, char* aH, int r0base, int colbase) {
#pragma unroll
    for (int mi = 0; mi < 2; mi++) {
        int r0 = r0base + mi * 16;
#pragma unroll
        for (int ni = 0; ni < 4; ni++) {
            int c = colbase + ni * 8;
            float bb0 = bias[c], bb1 = bias[c + 1];
            *(u32*)(aH + r0 * 272 + c * 2) =
                pkh2(ssp(acc[mi][ni][0] + bb0), ssp(acc[mi][ni][1] + bb1));
            *(u32*)(aH + (r0 + 8) * 272 + c * 2) =
                pkh2(ssp(acc[mi][ni][2] + bb0), ssp(acc[mi][ni][3] + bb1));
        }
    }
}

// ---------------- launch 1: weights + dist/C/hist + h init + out tail ----------------
__global__ void __launch_bounds__(256) k_prep_init(
        const float* __restrict__ pos, const int* __restrict__ ei,
        const int* __restrict__ atoms, const float* __restrict__ emb,
        const float* __restrict__ mw1, const float* __restrict__ mw2,
        const float* __restrict__ cw2, const float* __restrict__ iw,
        const float* __restrict__ cw1, float* __restrict__ out) {
    int idx = blockIdx.x * 256 + threadIdx.x;   // 0..EE-1
    if (idx < NLAYER * 128 * 128) {
        int l = idx >> 14, r = idx & 16383, n = r >> 7, k = r & 127;
        int sidx = (l * 128 + k) * 128 + n;
        g_w2t[idx]  = __float2half_rn(mw2[sidx]);
        g_cw2t[idx] = __float2half_rn(cw2[sidx]);
        g_iwt[idx]  = __float2half_rn(iw[sidx]);
        g_cw1t[idx] = __float2half_rn(cw1[sidx]);
    }
    if (idx < NLAYER * 128 * 64) {
        int l = idx >> 13, r = idx & 8191, n = r >> 6, k = r & 63;
        float v = (k < NGAUSS) ? mw1[(l * NGAUSS + k) * 128 + n] : 0.0f;
        g_w1t[idx] = __float2half_rn(v);
    }
    if (idx < 2 * GG) out[2 * NN + idx] = 0.0f;
    {
        int e = idx;
        int s = ei[e], d = ei[EE + e];
        float dx = pos[3*s]   - pos[3*d];
        float dy = pos[3*s+1] - pos[3*d+1];
        float dz = pos[3*s+2] - pos[3*d+2];
        float dist = sqrtf(dx*dx + dy*dy + dz*dz);
        g_dist[e] = dist;
        g_C[e] = 0.5f * (__cosf(dist * (3.14159265358979323846f / 10.0f)) + 1.0f);
        atomicAdd(&g_cnt[d], 1);
    }
    for (int j = idx; j < NN * 32; j += EE)
        ((float4*)g_h)[j] = ((const float4*)emb)[atoms[j >> 5] * 32 + (j & 31)];
}

// ---------------- fp32 f32x2 GEMM (layer-0 xl inside k_scan_xl) ----------------
template<int K>
__device__ __forceinline__ void gemm_tile(const float* __restrict__ As,
                                          const float* __restrict__ Bs,
                                          int ty, int tx, u64 acc[8][4]) {
    const float* ap = As + ty * 8;
    const float* bp = Bs + tx * 8;
#pragma unroll 4
    for (int k = 0; k < K; k++) {
        float4 a0 = *(const float4*)(ap + k * 132);
        float4 a1 = *(const float4*)(ap + k * 132 + 4);
        float4 b0 = *(const float4*)(bp + k * 128);
        float4 b1 = *(const float4*)(bp + k * 128 + 4);
        u64 bb0 = pk2(b0.x, b0.y), bb1 = pk2(b0.z, b0.w);
        u64 bb2 = pk2(b1.x, b1.y), bb3 = pk2(b1.z, b1.w);
        float a[8] = {a0.x, a0.y, a0.z, a0.w, a1.x, a1.y, a1.z, a1.w};
#pragma unroll
        for (int i = 0; i < 8; i++) {
            u64 aa = pk2(a[i], a[i]);
            fma2(acc[i][0], aa, bb0);
            fma2(acc[i][1], aa, bb1);
            fma2(acc[i][2], aa, bb2);
            fma2(acc[i][3], aa, bb3);
        }
    }
}
#define ZERO_ACC8F(acc) do { \
    _Pragma("unroll") for (int _i = 0; _i < 8; _i++) \
    _Pragma("unroll") for (int _j = 0; _j < 4; _j++) acc[_i][_j] = 0ull; } while (0)

// ---------------- launch 2: block 0 = scan (+ re-zero g_cnt), blocks 1.. = xl ----------------
__global__ void __launch_bounds__(256) k_scan_xl(const float* __restrict__ W) {
    if (blockIdx.x == 0) {
        __shared__ int warp_sums[8];
        __shared__ int s_carry;
        int tid = threadIdx.x;
        if (tid == 0) s_carry = 0;
        __syncthreads();
        for (int base = 0; base < NN; base += 256) {
            int i = base + tid;
            int v = (i < NN) ? g_cnt[i] : 0;
            int incl = v;
#pragma unroll
            for (int off = 1; off < 32; off <<= 1) {
                int n = __shfl_up_sync(0xffffffff, incl, off);
                if ((tid & 31) >= off) incl += n;
            }
            if ((tid & 31) == 31) warp_sums[tid >> 5] = incl;
            __syncthreads();
            if (tid < 8) {
                int ws = warp_sums[tid];
                int wi = ws;
#pragma unroll
                for (int off = 1; off < 8; off <<= 1) {
                    int n = __shfl_up_sync(0x000000ff, wi, off);
                    if (tid >= off) wi += n;
                }
                warp_sums[tid] = wi - ws;
            }
            __syncthreads();
            int excl = s_carry + warp_sums[tid >> 5] + incl - v;
            if (i < NN) g_cur[i] = excl;
            __syncthreads();
            if (tid == 255) s_carry = excl + v;
            __syncthreads();
        }
        for (int i = tid; i < NN; i += 256) g_cnt[i] = 0;
        return;
    }
    extern __shared__ float sm[];
    float* As = sm;
    float* Bs = As + 128 * 132;
    int tid = threadIdx.x, ty = tid >> 4, tx = tid & 15;
    int row0 = (blockIdx.x - 1) * 128;
    for (int i = tid; i < 128 * 32; i += 256) {
        int r = i & 127, kq = i >> 7;
        float4 v = make_float4(0.f, 0.f, 0.f, 0.f);
        int row = row0 + r;
        if (row < NN) v = *(const float4*)(g_h + (size_t)row * 128 + kq * 4);
        As[(kq*4+0)*132 + r] = v.x;
        As[(kq*4+1)*132 + r] = v.y;
        As[(kq*4+2)*132 + r] = v.z;
        As[(kq*4+3)*132 + r] = v.w;
    }
    for (int i = tid; i < 128 * 32; i += 256)
        ((float4*)Bs)[i] = ((const float4*)W)[i];
    __syncthreads();
    u64 acc[8][4]; ZERO_ACC8F(acc);
    gemm_tile<128>(As, Bs, ty, tx, acc);
#pragma unroll
    for (int i = 0; i < 8; i++) {
        int row = row0 + ty * 8 + i;
        if (row >= NN) continue;
        float v[8];
#pragma unroll
        for (int jp = 0; jp < 4; jp++) { float2 t2 = up2(acc[i][jp]); v[2*jp] = t2.x; v[2*jp+1] = t2.y; }
        *(float4*)(g_xl + (size_t)row * 128 + tx * 8)     = make_float4(v[0], v[1], v[2], v[3]);
        *(float4*)(g_xl + (size_t)row * 128 + tx * 8 + 4) = make_float4(v[4], v[5], v[6], v[7]);
    }
}

// ---------------- launch 3: permute edges into dst-sorted order ----------------
__global__ void __launch_bounds__(256) k_permute(const int* __restrict__ ei) {
    int e = blockIdx.x * 256 + threadIdx.x;
    if (e >= EE) return;
    int d = ei[EE + e];
    int pos = atomicAdd(&g_cur[d], 1);
    g_sd[pos]  = g_dist[e];
    g_sc[pos]  = g_C[e];
    g_ss[pos]  = ei[e];
    g_sdt[pos] = d;
}

// ---------------- edge pipeline: fp16 1-pass, 512 threads, fp32 msg ----------------
#define O_A1  0
#define O_B1  18432
#define O_A2  36864            // stride 272B
#define O_B2  71680
#define O_MSG 106496           // 128 rows x 512B (fp32 msg)
#define O_SB1 172032
#define O_SB2 172544
#define O_SCT 173056           // [2][128] f32
#define O_SRC 174080           // [2][128] i32
#define O_SDST 175104          // [2][128] i32
#define SMEM_EDGE 176128

// windowed gaussian quarter fill: thread owns gaussians [q*16, q*16+16) of one row
__device__ __forceinline__ void ea_fill_q(char* rowH, float dv, int q) {
    const float spc = 10.0f / 49.0f;
    const float coeff = -0.5f / (spc * spc);
    *(uint4*)(rowH + q * 32)      = make_uint4(0, 0, 0, 0);
    *(uint4*)(rowH + q * 32 + 16) = make_uint4(0, 0, 0, 0);
    float gf = dv * (49.0f / 10.0f);
    int gbeg = (int)(gf - 6.5f) + 1;
    if (gbeg < q * 16) gbeg = q * 16;
    int gend = (int)(gf + 6.5f);
    int glim = q * 16 + 15;
    if (glim > NGAUSS - 1) glim = NGAUSS - 1;
    if (gend > glim) gend = glim;
    for (int g = gbeg; g <= gend; g++) {
        float t = dv - (float)g * spc;
        *(__half*)(rowH + g * 2) = __float2half_rn(__expf(coeff * t * t));
    }
}

__global__ void __launch_bounds__(512, 1) k_edge_mma(
        int layer, const float* __restrict__ b1, const float* __restrict__ b2) {
    extern __shared__ char sp[];
    const u32 sbase = smem_u32(sp);
    int tid = threadIdx.x, lane = tid & 31, wid = tid >> 5;   // wid 0..15
    int wm = wid & 3, wn = wid >> 2;

    float* sb1f = (float*)(sp + O_SB1);
    float* sb2f = (float*)(sp + O_SB2);
    float* sct  = (float*)(sp + O_SCT);
    int*   ssrc = (int*)(sp + O_SRC);
    int*   sdst = (int*)(sp + O_SDST);

    // ---- weights to SMEM (once per launch) ----
    {
        const uint4* w1 = (const uint4*)(g_w1t + layer * 8192);
        for (int i = tid; i < 1024; i += 512) {
            int n = i >> 3, ch = i & 7;
            *(uint4*)(sp + O_B1 + n * 144 + ch * 16) = w1[i];
        }
        const uint4* w2 = (const uint4*)(g_w2t + layer * 16384);
        for (int i = tid; i < 2048; i += 512) {
            int n = i >> 4, ch = i & 15;
            *(uint4*)(sp + O_B2 + n * 272 + ch * 16) = w2[i];
        }
        if (tid < 128) { sb1f[tid] = b1[tid]; sb2f[tid] = b2[tid]; }
    }

    int a_r = (lane & 7) + ((lane >> 3) & 1) * 8;
    int a_k = (lane >> 4) * 8;
    int b_r = (lane & 7) + (lane >> 4) * 8;
    int b_k = ((lane >> 3) & 1) * 8;

    u32 A1_b = sbase + O_A1 + (u32)(wm * 32 + a_r) * 144 + (u32)a_k * 2;
    u32 B1_b = sbase + O_B1 + (u32)(wn * 32 + b_r) * 144 + (u32)b_k * 2;
    u32 A2_b = sbase + O_A2 + (u32)(wm * 32 + a_r) * 272 + (u32)a_k * 2;
    u32 B2_b = sbase + O_B2 + (u32)(wn * 32 + b_r) * 272 + (u32)b_k * 2;

    int r0base  = wm * 32 + (lane >> 2);
    int colbase = wn * 32 + (lane & 3) * 2;

    const int earow = tid >> 2, eaq = tid & 3;   // 4 threads per row

    // ---- prologue: EA + meta for first tile ----
    {
        int e0 = blockIdx.x * 128;
        ea_fill_q(sp + O_A1 + earow * 144, g_sd[e0 + earow], eaq);
        if (tid < 128) {
            ssrc[tid] = g_ss[e0 + tid];
            sdst[tid] = g_sdt[e0 + tid];
            sct[tid]  = g_sc[e0 + tid];
        }
    }
    __syncthreads();

    int pb = 0;
    for (int t = blockIdx.x; t < NTILES; t += EGRID, pb ^= 1) {
        float acc[2][4][4];
        ZACC4(acc);
        gemm_1p<4, 144>(acc, A1_b, B1_b);
        epi_ssp_h(acc, sb1f, sp + O_A2, r0base, colbase);
        __syncthreads();   // [A] A2 visible for GEMM2; A1 free for next EA

        int nt = t + EGRID;
        bool hasnext = nt < NTILES;
        float dv = 0.f, pm_c = 0.f;
        int pm_s = 0, pm_d = 0;
        if (hasnext) {
            dv = g_sd[nt * 128 + earow];
            if (tid < 128) {
                pm_s = g_ss[nt * 128 + tid];
                pm_d = g_sdt[nt * 128 + tid];
                pm_c = g_sc[nt * 128 + tid];
            }
        }

        ZACC4(acc);
        gemm_1p<8, 272>(acc, A2_b, B2_b);

        // ---- epi2: msg = (acc+b2)*C (fp32, own MSG bytes); no barrier needed ----
        const float* sctp = sct + pb * 128;
#pragma unroll
        for (int mi = 0; mi < 2; mi++) {
#pragma unroll
            for (int rr = 0; rr < 2; rr++) {
                int rt = r0base + mi * 16 + rr * 8;
                float ct = sctp[rt];
#pragma unroll
                for (int ni = 0; ni < 4; ni++) {
                    int cg = colbase + ni * 8;
                    float v0 = (acc[mi][ni][2*rr]     + sb2f[cg])     * ct;
                    float v1 = (acc[mi][ni][2*rr + 1] + sb2f[cg + 1]) * ct;
                    *(float2*)(sp + O_MSG + (u32)rt * 512 + (u32)cg * 4) = make_float2(v0, v1);
                }
            }
        }
        __syncwarp();

        // ---- scatter own 32 rows x 32 cols (before barrier; warp-private data) ----
        {
            const int* sso = ssrc + pb * 128;
            const int* sdo = sdst + pb * 128;
            int grp = lane >> 3, chunk = lane & 7;
            int rbeg = wm * 32 + grp * 8;
            u32 moff = (u32)O_MSG + (u32)(wn * 128) + (u32)(chunk * 16);
            int coff = wn * 32 + chunk * 4;
            float4 a4 = make_float4(0.f, 0.f, 0.f, 0.f);
            int cur = sdo[rbeg];
#pragma unroll
            for (int p4 = 0; p4 < 2; p4++) {
                int r0 = rbeg + p4 * 4;
                int sr[4], sd[4];
#pragma unroll
                for (int j = 0; j < 4; j++) { sr[j] = sso[r0 + j]; sd[j] = sdo[r0 + j]; }
                float4 x[4];
#pragma unroll
                for (int j = 0; j < 4; j++)
                    x[j] = *(const float4*)(g_xl + (size_t)sr[j] * 128 + coff);
#pragma unroll
                for (int j = 0; j < 4; j++) {
                    if (sd[j] != cur) {
                        red4(g_agg + (size_t)cur * 128 + coff, a4.x, a4.y, a4.z, a4.w);
                        a4 = make_float4(0.f, 0.f, 0.f, 0.f);
                        cur = sd[j];
                    }
                    float4 m = *(const float4*)(sp + moff + (u32)(r0 + j) * 512);
                    a4.x += m.x * x[j].x; a4.y += m.y * x[j].y;
                    a4.z += m.z * x[j].z; a4.w += m.w * x[j].w;
                }
            }
            red4(g_agg + (size_t)cur * 128 + coff, a4.x, a4.y, a4.z, a4.w);
        }

        // ---- EA fill for next tile (all 512 threads, quarter-rows) + meta ----
        if (hasnext) {
            ea_fill_q(sp + O_A1 + earow * 144, dv, eaq);
            int nb = (pb ^ 1) * 128;
            if (tid < 128) { ssrc[nb + tid] = pm_s; sdst[nb + tid] = pm_d; sct[nb + tid] = pm_c; }
        }
        __syncthreads();   // [B] GEMM2 A2-reads + scatter msg-reads done; EA/meta visible
    }
}

// ---------------- fused node update: fp16 1-pass, 512 threads ----------------
#define N_A  0
#define N_B  34816
#define SMEM_NODEM 69632

__global__ void __launch_bounds__(512, 1) k_node_mma(
        const float* __restrict__ cb2, const float* __restrict__ ib,
        int layer, int has_next) {
    extern __shared__ char sp[];
    const u32 sbase = smem_u32(sp);
    int tid = threadIdx.x, lane = tid & 31, wid = tid >> 5;
    int wm = wid & 3, wn = wid >> 2;
    int row0 = blockIdx.x * 128;

    int a_r = (lane & 7) + ((lane >> 3) & 1) * 8;
    int a_k = (lane >> 4) * 8;
    int b_r = (lane & 7) + (lane >> 4) * 8;
    int b_k = ((lane >> 3) & 1) * 8;
    u32 A_b = sbase + N_A + (u32)(wm * 32 + a_r) * 272 + (u32)a_k * 2;
    u32 B_b = sbase + N_B + (u32)(wn * 32 + b_r) * 272 + (u32)b_k * 2;
    int r0base  = wm * 32 + (lane >> 2);
    int colbase = wn * 32 + (lane & 3) * 2;

    // ---- A <- fp16(agg); zero agg; B <- cw2 ----
    for (int i = tid; i < 128 * 32; i += 512) {
        int r = i >> 5, c4 = i & 31;
        int row = row0 + r;
        float4 v = make_float4(0.f, 0.f, 0.f, 0.f);
        if (row < NN) {
            float* ap = g_agg + (size_t)row * 128 + c4 * 4;
            v = *(const float4*)ap;
            *(float4*)ap = make_float4(0.f, 0.f, 0.f, 0.f);
        }
        *(uint2*)(sp + N_A + r * 272 + c4 * 8) = make_uint2(pkh2(v.x, v.y), pkh2(v.z, v.w));
    }
    {
        const uint4* bh = (const uint4*)(g_cw2t + layer * 16384);
        for (int i = tid; i < 2048; i += 512) {
            int n = i >> 4, ch = i & 15;
            *(uint4*)(sp + N_B + n * 272 + ch * 16) = bh[i];
        }
    }
    __syncthreads();

    float acc[2][4][4];
    ZACC4(acc);
    gemm_1p<8, 272>(acc, A_b, B_b);
    __syncthreads();

    epi_ssp_h(acc, cb2, sp + N_A, r0base, colbase);
    {
        const uint4* bh = (const uint4*)(g_iwt + layer * 16384);
        for (int i = tid; i < 2048; i += 512) {
            int n = i >> 4, ch = i & 15;
            *(uint4*)(sp + N_B + n * 272 + ch * 16) = bh[i];
        }
    }
    __syncthreads();

    ZACC4(acc);
    gemm_1p<8, 272>(acc, A_b, B_b);
    __syncthreads();

    // ---- epi2: h += acc + ib ; A <- fp16(h_new) ----
#pragma unroll
    for (int mi = 0; mi < 2; mi++) {
        int r0 = r0base + mi * 16;
#pragma unroll
        for (int rr = 0; rr < 2; rr++) {
            int r = r0 + rr * 8;
            int row = row0 + r;
#pragma unroll
            for (int ni = 0; ni < 4; ni++) {
                int c = colbase + ni * 8;
                float v0 = acc[mi][ni][2*rr]     + ib[c];
                float v1 = acc[mi][ni][2*rr + 1] + ib[c + 1];
                float2 hv = make_float2(0.f, 0.f);
                float* hp = g_h + (size_t)row * 128 + c;
                if (row < NN) hv = *(const float2*)hp;
                hv.x += v0; hv.y += v1;
                if (row < NN) *(float2*)hp = hv;
                *(u32*)(sp + N_A + r * 272 + c * 2) = pkh2(hv.x, hv.y);
            }
        }
    }
    if (has_next) {
        const uint4* bh = (const uint4*)(g_cw1t + (layer + 1) * 16384);
        for (int i = tid; i < 2048; i += 512) {
            int n = i >> 4, ch = i & 15;
            *(uint4*)(sp + N_B + n * 272 + ch * 16) = bh[i];
        }
        __syncthreads();

        ZACC4(acc);
        gemm_1p<8, 272>(acc, A_b, B_b);

#pragma unroll
        for (int mi = 0; mi < 2; mi++) {
            int r0 = r0base + mi * 16;
#pragma unroll
            for (int rr = 0; rr < 2; rr++) {
                int row = row0 + r0 + rr * 8;
                if (row >= NN) continue;
#pragma unroll
                for (int ni = 0; ni < 4; ni++) {
                    int c = colbase + ni * 8;
                    *(float2*)(g_xl + (size_t)row * 128 + c) =
                        make_float2(acc[mi][ni][2*rr], acc[mi][ni][2*rr + 1]);
                }
            }
        }
    }
}

// ---------------- readout ----------------
__global__ void __launch_bounds__(128) k_read(const int* __restrict__ batch,
        const float* __restrict__ lw, const float* __restrict__ lb,
        const float* __restrict__ ew, const float* __restrict__ ebp,
        const float* __restrict__ qw, const float* __restrict__ qbp,
        float* __restrict__ out) {
    extern __shared__ float sm[];
    float* Hs  = sm;
    float* Ws  = Hs + 128 * 129;
    float* sb  = Ws + 128 * 64;
    float* sew = sb + 64;
    float* sqw = sew + 64;
    int tid = threadIdx.x;
    int row0 = blockIdx.x * 128;
    for (int i = tid; i < 128 * 128; i += 128) {
        int r = i >> 7, c = i & 127;
        int row = row0 + r;
        Hs[r * 129 + c] = (row < NN) ? g_h[(size_t)row * 128 + c] : 0.f;
    }
    for (int i = tid; i < 128 * 64; i += 128) Ws[i] = lw[i];
    if (tid < 64) { sb[tid] = lb[tid]; sew[tid] = ew[tid]; sqw[tid] = qw[tid]; }
    __syncthreads();
    int row = row0 + tid;
    if (row >= NN) return;
    float e = ebp[0], q = qbp[0];
    const float* hr = Hs + tid * 129;
#pragma unroll 2
    for (int j = 0; j < 64; j++) {
        float a = sb[j];
#pragma unroll 8
        for (int k = 0; k < 128; k++) a += hr[k] * Ws[k * 64 + j];
        float hh = ssp(a);
        e += hh * sew[j];
        q += hh * sqw[j];
    }
    out[row] = e;
    out[NN + row] = q;
    int b = batch[row];
    atomicAdd(out + 2 * NN + b, e);
    atomicAdd(out + 2 * NN + GG + b, q);
}

// ---------------- host ----------------
extern "C" void kernel_launch(void* const* d_in, const int* in_sizes, int n_in,
                              void* d_out, int out_size) {
    const int*   atoms = (const int*)d_in[0];
    const float* pos   = (const float*)d_in[1];
    const int*   batch = (const int*)d_in[2];
    const int*   ei    = (const int*)d_in[3];
    const float* emb   = (const float*)d_in[4];
    const float* mw1   = (const float*)d_in[5];
    const float* mb1   = (const float*)d_in[6];
    const float* mw2   = (const float*)d_in[7];
    const float* mb2   = (const float*)d_in[8];
    const float* cw1   = (const float*)d_in[9];
    const float* cw2   = (const float*)d_in[10];
    const float* cb2   = (const float*)d_in[11];
    const float* iw    = (const float*)d_in[12];
    const float* ib    = (const float*)d_in[13];
    const float* l1w   = (const float*)d_in[14];
    const float* l1b   = (const float*)d_in[15];
    const float* ew    = (const float*)d_in[16];
    const float* eb    = (const float*)d_in[17];
    const float* qw    = (const float*)d_in[18];
    const float* qb    = (const float*)d_in[19];
    float* out = (float*)d_out;

    constexpr int SMEM_GEMM = (128 * 132 + 128 * 128) * 4;
    constexpr int SMEM_READ = (128 * 129 + 128 * 64 + 192) * 4;

    cudaFuncSetAttribute(k_scan_xl,  cudaFuncAttributeMaxDynamicSharedMemorySize, SMEM_GEMM);
    cudaFuncSetAttribute(k_edge_mma, cudaFuncAttributeMaxDynamicSharedMemorySize, SMEM_EDGE);
    cudaFuncSetAttribute(k_node_mma, cudaFuncAttributeMaxDynamicSharedMemorySize, SMEM_NODEM);
    cudaFuncSetAttribute(k_read,     cudaFuncAttributeMaxDynamicSharedMemorySize, SMEM_READ);

    const int NODE_BLOCKS = (NN + 127) / 128;   // 391

    k_prep_init<<<EE / 256, 256>>>(pos, ei, atoms, emb, mw1, mw2, cw2, iw, cw1, out);
    k_scan_xl<<<NODE_BLOCKS + 1, 256, SMEM_GEMM>>>(cw1);
    k_permute<<<EE / 256, 256>>>(ei);

    for (int l = 0; l < NLAYER; l++) {
        k_edge_mma<<<EGRID, 512, SMEM_EDGE>>>(l, mb1 + (size_t)l * FF, mb2 + (size_t)l * FF);
        k_node_mma<<<NODE_BLOCKS, 512, SMEM_NODEM>>>(cb2 + (size_t)l * HH, ib + (size_t)l * HH,
                                                     l, (l < NLAYER - 1) ? 1 : 0);
    }
    k_read<<<NODE_BLOCKS, 128, SMEM_READ>>>(batch, l1w, l1b, ew, eb, qw, qb, out);
}

// round 14
// speedup vs baseline: 1.0213x; 1.0213x over previous
#include <cuda_runtime.h>
#include <cuda_fp16.h>
#include <cstdint>

#define NN 50000
#define EE 800000
#define GG 100
#define HH 128
#define FF 128
#define NGAUSS 50
#define NLAYER 6
#define NTILES (EE / 128)   // 6250
#define EGRID 148

typedef unsigned long long u64;
typedef unsigned int u32;

// ---------------- scratch (static device globals; no allocation) ----------------
__device__ float g_dist[EE];
__device__ float g_C[EE];
__device__ int   g_cnt[NN];     // re-zeroed by k_scan_xl each run
__device__ int   g_cur[NN];
__device__ float g_sd[EE];
__device__ float g_sc[EE];
__device__ int   g_ss[EE];
__device__ int   g_sdt[EE];
__device__ float g_h[(size_t)NN * HH];
__device__ float g_xl[(size_t)NN * FF];
__device__ float g_agg[(size_t)NN * FF];
// weights, fp16, [n][k] layout
__device__ __half g_w1t[NLAYER * 128 * 64];
__device__ __half g_w2t[NLAYER * 128 * 128];
__device__ __half g_cw2t[NLAYER * 128 * 128];
__device__ __half g_iwt[NLAYER * 128 * 128];
__device__ __half g_cw1t[NLAYER * 128 * 128];

// ---------------- generic helpers ----------------
__device__ __forceinline__ u64 pk2(float x, float y) {
    u64 r; asm("mov.b64 %0, {%1,%2};" : "=l"(r) : "f"(x), "f"(y)); return r;
}
__device__ __forceinline__ void fma2(u64& d, u64 a, u64 b) {
    asm("fma.rn.f32x2 %0, %1, %2, %0;" : "+l"(d) : "l"(a), "l"(b));
}
__device__ __forceinline__ float2 up2(u64 v) {
    float2 r; asm("mov.b64 {%0,%1}, %2;" : "=f"(r.x), "=f"(r.y) : "l"(v)); return r;
}
__device__ __forceinline__ void red4(float* p, float a, float b, float c, float d) {
    asm volatile("red.global.add.v4.f32 [%0], {%1,%2,%3,%4};"
                 :: "l"(p), "f"(a), "f"(b), "f"(c), "f"(d) : "memory");
}
__device__ __forceinline__ float ssp(float x) {
    return fmaxf(x, 0.0f) + __logf(1.0f + __expf(-fabsf(x))) - 0.69314718055994530942f;
}
__device__ __forceinline__ u32 smem_u32(const void* p) {
    u32 a; asm("{ .reg .u64 t; cvta.to.shared.u64 t, %1; cvt.u32.u64 %0, t; }" : "=r"(a) : "l"(p));
    return a;
}
__device__ __forceinline__ u32 pkh2(float x, float y) {
    __half2 t = __floats2half2_rn(x, y); return *(u32*)&t;
}

// ---------------- mma.sync fp16 helpers ----------------
__device__ __forceinline__ void ldmx4(u32* r, u32 addr) {
    asm volatile("ldmatrix.sync.aligned.m8n8.x4.shared.b16 {%0,%1,%2,%3}, [%4];"
                 : "=r"(r[0]), "=r"(r[1]), "=r"(r[2]), "=r"(r[3]) : "r"(addr));
}
__device__ __forceinline__ void mma16816(float* c, const u32* a, const u32* b) {
    asm volatile("mma.sync.aligned.m16n8k16.row.col.f32.f16.f16.f32 "
                 "{%0,%1,%2,%3}, {%4,%5,%6,%7}, {%8,%9}, {%0,%1,%2,%3};"
                 : "+f"(c[0]), "+f"(c[1]), "+f"(c[2]), "+f"(c[3])
                 : "r"(a[0]), "r"(a[1]), "r"(a[2]), "r"(a[3]), "r"(b[0]), "r"(b[1]));
}

#define ZACC4(acc) do { \
    _Pragma("unroll") for (int _m = 0; _m < 2; _m++) \
    _Pragma("unroll") for (int _n = 0; _n < 4; _n++) \
    _Pragma("unroll") for (int _q = 0; _q < 4; _q++) acc[_m][_n][_q] = 0.0f; } while (0)

// single-pass fp16 GEMM, warp tile 32x32 (2 m-frags x 2 n-frags)
template<int KS, int STRIDE>
__device__ __forceinline__ void gemm_1p(float acc[2][4][4], u32 Ab, u32 Bb) {
#pragma unroll
    for (int ks = 0; ks < KS; ks++) {
        u32 ah[2][4], bh[2][4];
        ldmx4(ah[0], Ab + ks * 32);
        ldmx4(ah[1], Ab + 16 * STRIDE + ks * 32);
        ldmx4(bh[0], Bb + ks * 32);
        ldmx4(bh[1], Bb + 16 * STRIDE + ks * 32);
#pragma unroll
        for (int mi = 0; mi < 2; mi++)
#pragma unroll
            for (int nb = 0; nb < 2; nb++) {
                mma16816(acc[mi][2*nb],   ah[mi], &bh[nb][0]);
                mma16816(acc[mi][2*nb+1], ah[mi], &bh[nb][2]);
            }
    }
}

// epilogue: ssp(acc + bias) -> fp16 into 272B-stride A buffer (own 32x32 subtile)
__device__ __forceinline__ void epi_ssp_h(const float acc[2][4][4],
        const float* bias, char* aH, int r0base, int colbase) {
#pragma unroll
    for (int mi = 0; mi < 2; mi++) {
        int r0 = r0base + mi * 16;
#pragma unroll
        for (int ni = 0; ni < 4; ni++) {
            int c = colbase + ni * 8;
            float bb0 = bias[c], bb1 = bias[c + 1];
            *(u32*)(aH + r0 * 272 + c * 2) =
                pkh2(ssp(acc[mi][ni][0] + bb0), ssp(acc[mi][ni][1] + bb1));
            *(u32*)(aH + (r0 + 8) * 272 + c * 2) =
                pkh2(ssp(acc[mi][ni][2] + bb0), ssp(acc[mi][ni][3] + bb1));
        }
    }
}

// ---------------- launch 1: weights + dist/C/hist + h init + out tail ----------------
__global__ void __launch_bounds__(256) k_prep_init(
        const float* __restrict__ pos, const int* __restrict__ ei,
        const int* __restrict__ atoms, const float* __restrict__ emb,
        const float* __restrict__ mw1, const float* __restrict__ mw2,
        const float* __restrict__ cw2, const float* __restrict__ iw,
        const float* __restrict__ cw1, float* __restrict__ out) {
    int idx = blockIdx.x * 256 + threadIdx.x;   // 0..EE-1
    if (idx < NLAYER * 128 * 128) {
        int l = idx >> 14, r = idx & 16383, n = r >> 7, k = r & 127;
        int sidx = (l * 128 + k) * 128 + n;
        g_w2t[idx]  = __float2half_rn(mw2[sidx]);
        g_cw2t[idx] = __float2half_rn(cw2[sidx]);
        g_iwt[idx]  = __float2half_rn(iw[sidx]);
        g_cw1t[idx] = __float2half_rn(cw1[sidx]);
    }
    if (idx < NLAYER * 128 * 64) {
        int l = idx >> 13, r = idx & 8191, n = r >> 6, k = r & 63;
        float v = (k < NGAUSS) ? mw1[(l * NGAUSS + k) * 128 + n] : 0.0f;
        g_w1t[idx] = __float2half_rn(v);
    }
    if (idx < 2 * GG) out[2 * NN + idx] = 0.0f;
    {
        int e = idx;
        int s = ei[e], d = ei[EE + e];
        float dx = pos[3*s]   - pos[3*d];
        float dy = pos[3*s+1] - pos[3*d+1];
        float dz = pos[3*s+2] - pos[3*d+2];
        float dist = sqrtf(dx*dx + dy*dy + dz*dz);
        g_dist[e] = dist;
        g_C[e] = 0.5f * (__cosf(dist * (3.14159265358979323846f / 10.0f)) + 1.0f);
        atomicAdd(&g_cnt[d], 1);
    }
    for (int j = idx; j < NN * 32; j += EE)
        ((float4*)g_h)[j] = ((const float4*)emb)[atoms[j >> 5] * 32 + (j & 31)];
}

// ---------------- fp32 f32x2 GEMM (layer-0 xl inside k_scan_xl) ----------------
template<int K>
__device__ __forceinline__ void gemm_tile(const float* __restrict__ As,
                                          const float* __restrict__ Bs,
                                          int ty, int tx, u64 acc[8][4]) {
    const float* ap = As + ty * 8;
    const float* bp = Bs + tx * 8;
#pragma unroll 4
    for (int k = 0; k < K; k++) {
        float4 a0 = *(const float4*)(ap + k * 132);
        float4 a1 = *(const float4*)(ap + k * 132 + 4);
        float4 b0 = *(const float4*)(bp + k * 128);
        float4 b1 = *(const float4*)(bp + k * 128 + 4);
        u64 bb0 = pk2(b0.x, b0.y), bb1 = pk2(b0.z, b0.w);
        u64 bb2 = pk2(b1.x, b1.y), bb3 = pk2(b1.z, b1.w);
        float a[8] = {a0.x, a0.y, a0.z, a0.w, a1.x, a1.y, a1.z, a1.w};
#pragma unroll
        for (int i = 0; i < 8; i++) {
            u64 aa = pk2(a[i], a[i]);
            fma2(acc[i][0], aa, bb0);
            fma2(acc[i][1], aa, bb1);
            fma2(acc[i][2], aa, bb2);
            fma2(acc[i][3], aa, bb3);
        }
    }
}
#define ZERO_ACC8F(acc) do { \
    _Pragma("unroll") for (int _i = 0; _i < 8; _i++) \
    _Pragma("unroll") for (int _j = 0; _j < 4; _j++) acc[_i][_j] = 0ull; } while (0)

// ---------------- launch 2: block 0 = scan (+ re-zero g_cnt), blocks 1.. = xl ----------------
__global__ void __launch_bounds__(256) k_scan_xl(const float* __restrict__ W) {
    if (blockIdx.x == 0) {
        __shared__ int warp_sums[8];
        __shared__ int s_carry;
        int tid = threadIdx.x;
        if (tid == 0) s_carry = 0;
        __syncthreads();
        for (int base = 0; base < NN; base += 256) {
            int i = base + tid;
            int v = (i < NN) ? g_cnt[i] : 0;
            int incl = v;
#pragma unroll
            for (int off = 1; off < 32; off <<= 1) {
                int n = __shfl_up_sync(0xffffffff, incl, off);
                if ((tid & 31) >= off) incl += n;
            }
            if ((tid & 31) == 31) warp_sums[tid >> 5] = incl;
            __syncthreads();
            if (tid < 8) {
                int ws = warp_sums[tid];
                int wi = ws;
#pragma unroll
                for (int off = 1; off < 8; off <<= 1) {
                    int n = __shfl_up_sync(0x000000ff, wi, off);
                    if (tid >= off) wi += n;
                }
                warp_sums[tid] = wi - ws;
            }
            __syncthreads();
            int excl = s_carry + warp_sums[tid >> 5] + incl - v;
            if (i < NN) g_cur[i] = excl;
            __syncthreads();
            if (tid == 255) s_carry = excl + v;
            __syncthreads();
        }
        for (int i = tid; i < NN; i += 256) g_cnt[i] = 0;
        return;
    }
    extern __shared__ float sm[];
    float* As = sm;
    float* Bs = As + 128 * 132;
    int tid = threadIdx.x, ty = tid >> 4, tx = tid & 15;
    int row0 = (blockIdx.x - 1) * 128;
    for (int i = tid; i < 128 * 32; i += 256) {
        int r = i & 127, kq = i >> 7;
        float4 v = make_float4(0.f, 0.f, 0.f, 0.f);
        int row = row0 + r;
        if (row < NN) v = *(const float4*)(g_h + (size_t)row * 128 + kq * 4);
        As[(kq*4+0)*132 + r] = v.x;
        As[(kq*4+1)*132 + r] = v.y;
        As[(kq*4+2)*132 + r] = v.z;
        As[(kq*4+3)*132 + r] = v.w;
    }
    for (int i = tid; i < 128 * 32; i += 256)
        ((float4*)Bs)[i] = ((const float4*)W)[i];
    __syncthreads();
    u64 acc[8][4]; ZERO_ACC8F(acc);
    gemm_tile<128>(As, Bs, ty, tx, acc);
#pragma unroll
    for (int i = 0; i < 8; i++) {
        int row = row0 + ty * 8 + i;
        if (row >= NN) continue;
        float v[8];
#pragma unroll
        for (int jp = 0; jp < 4; jp++) { float2 t2 = up2(acc[i][jp]); v[2*jp] = t2.x; v[2*jp+1] = t2.y; }
        *(float4*)(g_xl + (size_t)row * 128 + tx * 8)     = make_float4(v[0], v[1], v[2], v[3]);
        *(float4*)(g_xl + (size_t)row * 128 + tx * 8 + 4) = make_float4(v[4], v[5], v[6], v[7]);
    }
}

// ---------------- launch 3: permute edges into dst-sorted order ----------------
__global__ void __launch_bounds__(256) k_permute(const int* __restrict__ ei) {
    int e = blockIdx.x * 256 + threadIdx.x;
    if (e >= EE) return;
    int d = ei[EE + e];
    int pos = atomicAdd(&g_cur[d], 1);
    g_sd[pos]  = g_dist[e];
    g_sc[pos]  = g_C[e];
    g_ss[pos]  = ei[e];
    g_sdt[pos] = d;
}

// ---------------- edge pipeline: fp16 1-pass, 512 threads, fp32 msg (R9 struct) ----------------
#define O_A1  0
#define O_B1  18432
#define O_A2  36864            // stride 272B
#define O_B2  71680
#define O_MSG 106496           // 128 rows x 512B (fp32 msg)
#define O_SB1 172032
#define O_SB2 172544
#define O_SCT 173056           // [2][128] f32
#define O_SRC 174080           // [2][128] i32
#define O_SDST 175104          // [2][128] i32
#define SMEM_EDGE 176128

// windowed gaussian half-row fill: thread owns gaussians [h*32, h*32+32) of one row
__device__ __forceinline__ void ea_fill_h(char* rowH, float dv, int h) {
    const float spc = 10.0f / 49.0f;
    const float coeff = -0.5f / (spc * spc);
#pragma unroll
    for (int q = 0; q < 4; q++) *(uint4*)(rowH + h * 64 + q * 16) = make_uint4(0, 0, 0, 0);
    float gf = dv * (49.0f / 10.0f);
    int gbeg = (int)(gf - 6.5f) + 1;
    if (gbeg < h * 32) gbeg = h * 32;
    int gend = (int)(gf + 6.5f);
    int glim = h * 32 + 31;
    if (glim > NGAUSS - 1) glim = NGAUSS - 1;
    if (gend > glim) gend = glim;
    for (int g = gbeg; g <= gend; g++) {
        float t = dv - (float)g * spc;
        *(__half*)(rowH + g * 2) = __float2half_rn(__expf(coeff * t * t));
    }
}

__global__ void __launch_bounds__(512, 1) k_edge_mma(
        int layer, const float* __restrict__ b1, const float* __restrict__ b2) {
    extern __shared__ char sp[];
    const u32 sbase = smem_u32(sp);
    int tid = threadIdx.x, lane = tid & 31, wid = tid >> 5;   // wid 0..15
    int wm = wid & 3, wn = wid >> 2;

    float* sb1f = (float*)(sp + O_SB1);
    float* sb2f = (float*)(sp + O_SB2);
    float* sct  = (float*)(sp + O_SCT);
    int*   ssrc = (int*)(sp + O_SRC);
    int*   sdst = (int*)(sp + O_SDST);

    // ---- weights to SMEM (once per launch) ----
    {
        const uint4* w1 = (const uint4*)(g_w1t + layer * 8192);
        for (int i = tid; i < 1024; i += 512) {
            int n = i >> 3, ch = i & 7;
            *(uint4*)(sp + O_B1 + n * 144 + ch * 16) = w1[i];
        }
        const uint4* w2 = (const uint4*)(g_w2t + layer * 16384);
        for (int i = tid; i < 2048; i += 512) {
            int n = i >> 4, ch = i & 15;
            *(uint4*)(sp + O_B2 + n * 272 + ch * 16) = w2[i];
        }
        if (tid < 128) { sb1f[tid] = b1[tid]; sb2f[tid] = b2[tid]; }
    }

    int a_r = (lane & 7) + ((lane >> 3) & 1) * 8;
    int a_k = (lane >> 4) * 8;
    int b_r = (lane & 7) + (lane >> 4) * 8;
    int b_k = ((lane >> 3) & 1) * 8;

    u32 A1_b = sbase + O_A1 + (u32)(wm * 32 + a_r) * 144 + (u32)a_k * 2;
    u32 B1_b = sbase + O_B1 + (u32)(wn * 32 + b_r) * 144 + (u32)b_k * 2;
    u32 A2_b = sbase + O_A2 + (u32)(wm * 32 + a_r) * 272 + (u32)a_k * 2;
    u32 B2_b = sbase + O_B2 + (u32)(wn * 32 + b_r) * 272 + (u32)b_k * 2;

    int r0base  = wm * 32 + (lane >> 2);
    int colbase = wn * 32 + (lane & 3) * 2;

    const int earow = tid >> 1, eah = tid & 1;   // 2 threads per row (rows 0..255 -> tid<256)

    // ---- prologue: EA + meta for first tile ----
    {
        int e0 = blockIdx.x * 128;
        if (tid < 256) ea_fill_h(sp + O_A1 + earow * 144, g_sd[e0 + earow], eah);
        if (tid < 128) {
            ssrc[tid] = g_ss[e0 + tid];
            sdst[tid] = g_sdt[e0 + tid];
            sct[tid]  = g_sc[e0 + tid];
        }
    }
    __syncthreads();

    int pb = 0;
    for (int t = blockIdx.x; t < NTILES; t += EGRID, pb ^= 1) {
        float acc[2][4][4];
        ZACC4(acc);
        gemm_1p<4, 144>(acc, A1_b, B1_b);
        epi_ssp_h(acc, sb1f, sp + O_A2, r0base, colbase);
        __syncthreads();   // [A] A2 visible for GEMM2; A1 free for next EA

        int nt = t + EGRID;
        bool hasnext = nt < NTILES;
        float dv = 0.f, pm_c = 0.f;
        int pm_s = 0, pm_d = 0;
        if (hasnext) {
            if (tid < 256) dv = g_sd[nt * 128 + earow];
            if (tid < 128) {
                pm_s = g_ss[nt * 128 + tid];
                pm_d = g_sdt[nt * 128 + tid];
                pm_c = g_sc[nt * 128 + tid];
            }
        }

        ZACC4(acc);
        gemm_1p<8, 272>(acc, A2_b, B2_b);

        if (hasnext) {
            if (tid < 256) ea_fill_h(sp + O_A1 + earow * 144, dv, eah);
            int nb = (pb ^ 1) * 128;
            if (tid < 128) { ssrc[nb + tid] = pm_s; sdst[nb + tid] = pm_d; sct[nb + tid] = pm_c; }
        }
        __syncthreads();   // [B] GEMM2 A2-reads done; EA/meta visible for next iter

        // ---- epi2: msg = (acc+b2)*C -> fp32 into own MSG bytes ----
        const float* sctp = sct + pb * 128;
#pragma unroll
        for (int mi = 0; mi < 2; mi++) {
#pragma unroll
            for (int rr = 0; rr < 2; rr++) {
                int rt = r0base + mi * 16 + rr * 8;
                float ct = sctp[rt];
#pragma unroll
                for (int ni = 0; ni < 4; ni++) {
                    int cg = colbase + ni * 8;
                    float v0 = (acc[mi][ni][2*rr]     + sb2f[cg])     * ct;
                    float v1 = (acc[mi][ni][2*rr + 1] + sb2f[cg + 1]) * ct;
                    *(float2*)(sp + O_MSG + (u32)rt * 512 + (u32)cg * 4) = make_float2(v0, v1);
                }
            }
        }
        __syncwarp();

        // ---- scatter own 32 rows x 32 cols; overlaps next GEMM1 (no barrier after) ----
        {
            const int* sso = ssrc + pb * 128;
            const int* sdo = sdst + pb * 128;
            int grp = lane >> 3, chunk = lane & 7;
            int rbeg = wm * 32 + grp * 8;
            u32 moff = (u32)O_MSG + (u32)(wn * 128) + (u32)(chunk * 16);
            int coff = wn * 32 + chunk * 4;
            float4 a4 = make_float4(0.f, 0.f, 0.f, 0.f);
            int cur = sdo[rbeg];
#pragma unroll
            for (int p4 = 0; p4 < 2; p4++) {
                int r0 = rbeg + p4 * 4;
                int sr[4], sd[4];
#pragma unroll
                for (int j = 0; j < 4; j++) { sr[j] = sso[r0 + j]; sd[j] = sdo[r0 + j]; }
                float4 x[4];
#pragma unroll
                for (int j = 0; j < 4; j++)
                    x[j] = *(const float4*)(g_xl + (size_t)sr[j] * 128 + coff);
#pragma unroll
                for (int j = 0; j < 4; j++) {
                    if (sd[j] != cur) {
                        red4(g_agg + (size_t)cur * 128 + coff, a4.x, a4.y, a4.z, a4.w);
                        a4 = make_float4(0.f, 0.f, 0.f, 0.f);
                        cur = sd[j];
                    }
                    float4 m = *(const float4*)(sp + moff + (u32)(r0 + j) * 512);
                    a4.x += m.x * x[j].x; a4.y += m.y * x[j].y;
                    a4.z += m.z * x[j].z; a4.w += m.w * x[j].w;
                }
            }
            red4(g_agg + (size_t)cur * 128 + coff, a4.x, a4.y, a4.z, a4.w);
        }
    }
}

// ---------------- fused node update: fp16 1-pass, 512 threads ----------------
#define N_A  0
#define N_B  34816
#define SMEM_NODEM 69632

__global__ void __launch_bounds__(512, 1) k_node_mma(
        const float* __restrict__ cb2, const float* __restrict__ ib,
        int layer, int has_next) {
    extern __shared__ char sp[];
    const u32 sbase = smem_u32(sp);
    int tid = threadIdx.x, lane = tid & 31, wid = tid >> 5;
    int wm = wid & 3, wn = wid >> 2;
    int row0 = blockIdx.x * 128;

    int a_r = (lane & 7) + ((lane >> 3) & 1) * 8;
    int a_k = (lane >> 4) * 8;
    int b_r = (lane & 7) + (lane >> 4) * 8;
    int b_k = ((lane >> 3) & 1) * 8;
    u32 A_b = sbase + N_A + (u32)(wm * 32 + a_r) * 272 + (u32)a_k * 2;
    u32 B_b = sbase + N_B + (u32)(wn * 32 + b_r) * 272 + (u32)b_k * 2;
    int r0base  = wm * 32 + (lane >> 2);
    int colbase = wn * 32 + (lane & 3) * 2;

    // ---- A <- fp16(agg); zero agg; B <- cw2 ----
    for (int i = tid; i < 128 * 32; i += 512) {
        int r = i >> 5, c4 = i & 31;
        int row = row0 + r;
        float4 v = make_float4(0.f, 0.f, 0.f, 0.f);
        if (row < NN) {
            float* ap = g_agg + (size_t)row * 128 + c4 * 4;
            v = *(const float4*)ap;
            *(float4*)ap = make_float4(0.f, 0.f, 0.f, 0.f);
        }
        *(uint2*)(sp + N_A + r * 272 + c4 * 8) = make_uint2(pkh2(v.x, v.y), pkh2(v.z, v.w));
    }
    {
        const uint4* bh = (const uint4*)(g_cw2t + layer * 16384);
        for (int i = tid; i < 2048; i += 512) {
            int n = i >> 4, ch = i & 15;
            *(uint4*)(sp + N_B + n * 272 + ch * 16) = bh[i];
        }
    }
    __syncthreads();

    float acc[2][4][4];
    ZACC4(acc);
    gemm_1p<8, 272>(acc, A_b, B_b);
    __syncthreads();

    epi_ssp_h(acc, cb2, sp + N_A, r0base, colbase);
    {
        const uint4* bh = (const uint4*)(g_iwt + layer * 16384);
        for (int i = tid; i < 2048; i += 512) {
            int n = i >> 4, ch = i & 15;
            *(uint4*)(sp + N_B + n * 272 + ch * 16) = bh[i];
        }
    }
    __syncthreads();

    ZACC4(acc);
    gemm_1p<8, 272>(acc, A_b, B_b);
    __syncthreads();

    // ---- epi2: h += acc + ib ; A <- fp16(h_new) ----
#pragma unroll
    for (int mi = 0; mi < 2; mi++) {
        int r0 = r0base + mi * 16;
#pragma unroll
        for (int rr = 0; rr < 2; rr++) {
            int r = r0 + rr * 8;
            int row = row0 + r;
#pragma unroll
            for (int ni = 0; ni < 4; ni++) {
                int c = colbase + ni * 8;
                float v0 = acc[mi][ni][2*rr]     + ib[c];
                float v1 = acc[mi][ni][2*rr + 1] + ib[c + 1];
                float2 hv = make_float2(0.f, 0.f);
                float* hp = g_h + (size_t)row * 128 + c;
                if (row < NN) hv = *(const float2*)hp;
                hv.x += v0; hv.y += v1;
                if (row < NN) *(float2*)hp = hv;
                *(u32*)(sp + N_A + r * 272 + c * 2) = pkh2(hv.x, hv.y);
            }
        }
    }
    if (has_next) {
        const uint4* bh = (const uint4*)(g_cw1t + (layer + 1) * 16384);
        for (int i = tid; i < 2048; i += 512) {
            int n = i >> 4, ch = i & 15;
            *(uint4*)(sp + N_B + n * 272 + ch * 16) = bh[i];
        }
        __syncthreads();

        ZACC4(acc);
        gemm_1p<8, 272>(acc, A_b, B_b);

#pragma unroll
        for (int mi = 0; mi < 2; mi++) {
            int r0 = r0base + mi * 16;
#pragma unroll
            for (int rr = 0; rr < 2; rr++) {
                int row = row0 + r0 + rr * 8;
                if (row >= NN) continue;
#pragma unroll
                for (int ni = 0; ni < 4; ni++) {
                    int c = colbase + ni * 8;
                    *(float2*)(g_xl + (size_t)row * 128 + c) =
                        make_float2(acc[mi][ni][2*rr], acc[mi][ni][2*rr + 1]);
                }
            }
        }
    }
}

// ---------------- readout ----------------
__global__ void __launch_bounds__(128) k_read(const int* __restrict__ batch,
        const float* __restrict__ lw, const float* __restrict__ lb,
        const float* __restrict__ ew, const float* __restrict__ ebp,
        const float* __restrict__ qw, const float* __restrict__ qbp,
        float* __restrict__ out) {
    extern __shared__ float sm[];
    float* Hs  = sm;
    float* Ws  = Hs + 128 * 129;
    float* sb  = Ws + 128 * 64;
    float* sew = sb + 64;
    float* sqw = sew + 64;
    int tid = threadIdx.x;
    int row0 = blockIdx.x * 128;
    for (int i = tid; i < 128 * 128; i += 128) {
        int r = i >> 7, c = i & 127;
        int row = row0 + r;
        Hs[r * 129 + c] = (row < NN) ? g_h[(size_t)row * 128 + c] : 0.f;
    }
    for (int i = tid; i < 128 * 64; i += 128) Ws[i] = lw[i];
    if (tid < 64) { sb[tid] = lb[tid]; sew[tid] = ew[tid]; sqw[tid] = qw[tid]; }
    __syncthreads();
    int row = row0 + tid;
    if (row >= NN) return;
    float e = ebp[0], q = qbp[0];
    const float* hr = Hs + tid * 129;
#pragma unroll 2
    for (int j = 0; j < 64; j++) {
        float a = sb[j];
#pragma unroll 8
        for (int k = 0; k < 128; k++) a += hr[k] * Ws[k * 64 + j];
        float hh = ssp(a);
        e += hh * sew[j];
        q += hh * sqw[j];
    }
    out[row] = e;
    out[NN + row] = q;
    int b = batch[row];
    atomicAdd(out + 2 * NN + b, e);
    atomicAdd(out + 2 * NN + GG + b, q);
}

// ---------------- host ----------------
extern "C" void kernel_launch(void* const* d_in, const int* in_sizes, int n_in,
                              void* d_out, int out_size) {
    const int*   atoms = (const int*)d_in[0];
    const float* pos   = (const float*)d_in[1];
    const int*   batch = (const int*)d_in[2];
    const int*   ei    = (const int*)d_in[3];
    const float* emb   = (const float*)d_in[4];
    const float* mw1   = (const float*)d_in[5];
    const float* mb1   = (const float*)d_in[6];
    const float* mw2   = (const float*)d_in[7];
    const float* mb2   = (const float*)d_in[8];
    const float* cw1   = (const float*)d_in[9];
    const float* cw2   = (const float*)d_in[10];
    const float* cb2   = (const float*)d_in[11];
    const float* iw    = (const float*)d_in[12];
    const float* ib    = (const float*)d_in[13];
    const float* l1w   = (const float*)d_in[14];
    const float* l1b   = (const float*)d_in[15];
    const float* ew    = (const float*)d_in[16];
    const float* eb    = (const float*)d_in[17];
    const float* qw    = (const float*)d_in[18];
    const float* qb    = (const float*)d_in[19];
    float* out = (float*)d_out;

    constexpr int SMEM_GEMM = (128 * 132 + 128 * 128) * 4;
    constexpr int SMEM_READ = (128 * 129 + 128 * 64 + 192) * 4;

    cudaFuncSetAttribute(k_scan_xl,  cudaFuncAttributeMaxDynamicSharedMemorySize, SMEM_GEMM);
    cudaFuncSetAttribute(k_edge_mma, cudaFuncAttributeMaxDynamicSharedMemorySize, SMEM_EDGE);
    cudaFuncSetAttribute(k_node_mma, cudaFuncAttributeMaxDynamicSharedMemorySize, SMEM_NODEM);
    cudaFuncSetAttribute(k_read,     cudaFuncAttributeMaxDynamicSharedMemorySize, SMEM_READ);

    const int NODE_BLOCKS = (NN + 127) / 128;   // 391

    k_prep_init<<<EE / 256, 256>>>(pos, ei, atoms, emb, mw1, mw2, cw2, iw, cw1, out);
    k_scan_xl<<<NODE_BLOCKS + 1, 256, SMEM_GEMM>>>(cw1);
    k_permute<<<EE / 256, 256>>>(ei);

    for (int l = 0; l < NLAYER; l++) {
        k_edge_mma<<<EGRID, 512, SMEM_EDGE>>>(l, mb1 + (size_t)l * FF, mb2 + (size_t)l * FF);
        k_node_mma<<<NODE_BLOCKS, 512, SMEM_NODEM>>>(cb2 + (size_t)l * HH, ib + (size_t)l * HH,
                                                     l, (l < NLAYER - 1) ? 1 : 0);
    }
    k_read<<<NODE_BLOCKS, 128, SMEM_READ>>>(batch, l1w, l1b, ew, eb, qw, qb, out);
}

// round 17
// speedup vs baseline: 1.0582x; 1.0361x over previous
#include <cuda_runtime.h>
#include <cuda_fp16.h>
#include <cstdint>

#define NN 50000
#define EE 800000
#define GG 100
#define HH 128
#define FF 128
#define NGAUSS 50
#define NLAYER 6
#define NTILES (EE / 128)   // 6250
#define EGRID 148

typedef unsigned long long u64;
typedef unsigned int u32;

// ---------------- scratch (static device globals; no allocation) ----------------
__device__ float g_dist[EE];
__device__ float g_C[EE];
__device__ int   g_cnt[NN];     // re-zeroed by k_scan each run
__device__ int   g_cur[NN];
__device__ float g_sd[EE];
__device__ float g_sc[EE];
__device__ int   g_ss[EE];
__device__ int   g_sdt[EE];
__device__ float g_h[(size_t)NN * HH];
__device__ float g_xl[(size_t)NN * FF];
__device__ float g_agg[(size_t)NN * FF];
// weights, fp16, [n][k] layout
__device__ __half g_w1t[NLAYER * 128 * 64];
__device__ __half g_w2t[NLAYER * 128 * 128];
__device__ __half g_cw2t[NLAYER * 128 * 128];
__device__ __half g_iwt[NLAYER * 128 * 128];
__device__ __half g_cw1t[NLAYER * 128 * 128];

// ---------------- generic helpers ----------------
__device__ __forceinline__ void red4(float* p, float a, float b, float c, float d) {
    asm volatile("red.global.add.v4.f32 [%0], {%1,%2,%3,%4};"
                 :: "l"(p), "f"(a), "f"(b), "f"(c), "f"(d) : "memory");
}
__device__ __forceinline__ float ssp(float x) {
    return fmaxf(x, 0.0f) + __logf(1.0f + __expf(-fabsf(x))) - 0.69314718055994530942f;
}
__device__ __forceinline__ u32 smem_u32(const void* p) {
    u32 a; asm("{ .reg .u64 t; cvta.to.shared.u64 t, %1; cvt.u32.u64 %0, t; }" : "=r"(a) : "l"(p));
    return a;
}
__device__ __forceinline__ u32 pkh2(float x, float y) {
    __half2 t = __floats2half2_rn(x, y); return *(u32*)&t;
}

// ---------------- mma.sync fp16 helpers ----------------
__device__ __forceinline__ void ldmx4(u32* r, u32 addr) {
    asm volatile("ldmatrix.sync.aligned.m8n8.x4.shared.b16 {%0,%1,%2,%3}, [%4];"
                 : "=r"(r[0]), "=r"(r[1]), "=r"(r[2]), "=r"(r[3]) : "r"(addr));
}
__device__ __forceinline__ void mma16816(float* c, const u32* a, const u32* b) {
    asm volatile("mma.sync.aligned.m16n8k16.row.col.f32.f16.f16.f32 "
                 "{%0,%1,%2,%3}, {%4,%5,%6,%7}, {%8,%9}, {%0,%1,%2,%3};"
                 : "+f"(c[0]), "+f"(c[1]), "+f"(c[2]), "+f"(c[3])
                 : "r"(a[0]), "r"(a[1]), "r"(a[2]), "r"(a[3]), "r"(b[0]), "r"(b[1]));
}

#define ZACC4(acc) do { \
    _Pragma("unroll") for (int _m = 0; _m < 2; _m++) \
    _Pragma("unroll") for (int _n = 0; _n < 4; _n++) \
    _Pragma("unroll") for (int _q = 0; _q < 4; _q++) acc[_m][_n][_q] = 0.0f; } while (0)

// single-pass fp16 GEMM, warp tile 32x32 (2 m-frags x 2 n-frags)
template<int KS, int STRIDE>
__device__ __forceinline__ void gemm_1p(float acc[2][4][4], u32 Ab, u32 Bb) {
#pragma unroll
    for (int ks = 0; ks < KS; ks++) {
        u32 ah[2][4], bh[2][4];
        ldmx4(ah[0], Ab + ks * 32);
        ldmx4(ah[1], Ab + 16 * STRIDE + ks * 32);
        ldmx4(bh[0], Bb + ks * 32);
        ldmx4(bh[1], Bb + 16 * STRIDE + ks * 32);
#pragma unroll
        for (int mi = 0; mi < 2; mi++)
#pragma unroll
            for (int nb = 0; nb < 2; nb++) {
                mma16816(acc[mi][2*nb],   ah[mi], &bh[nb][0]);
                mma16816(acc[mi][2*nb+1], ah[mi], &bh[nb][2]);
            }
    }
}

// epilogue: ssp(acc + bias) -> fp16 into 272B-stride A buffer (own 32x32 subtile)
__device__ __forceinline__ void epi_ssp_h(const float acc[2][4][4],
        const float* bias, char* aH, int r0base, int colbase) {
#pragma unroll
    for (int mi = 0; mi < 2; mi++) {
        int r0 = r0base + mi * 16;
#pragma unroll
        for (int ni = 0; ni < 4; ni++) {
            int c = colbase + ni * 8;
            float bb0 = bias[c], bb1 = bias[c + 1];
            *(u32*)(aH + r0 * 272 + c * 2) =
                pkh2(ssp(acc[mi][ni][0] + bb0), ssp(acc[mi][ni][1] + bb1));
            *(u32*)(aH + (r0 + 8) * 272 + c * 2) =
                pkh2(ssp(acc[mi][ni][2] + bb0), ssp(acc[mi][ni][3] + bb1));
        }
    }
}

// ---------------- launch 1: weights + dist/C/hist + h init + out tail ----------------
__global__ void __launch_bounds__(256) k_prep_init(
        const float* __restrict__ pos, const int* __restrict__ ei,
        const int* __restrict__ atoms, const float* __restrict__ emb,
        const float* __restrict__ mw1, const float* __restrict__ mw2,
        const float* __restrict__ cw2, const float* __restrict__ iw,
        const float* __restrict__ cw1, float* __restrict__ out) {
    int idx = blockIdx.x * 256 + threadIdx.x;   // 0..EE-1
    if (idx < NLAYER * 128 * 128) {
        int l = idx >> 14, r = idx & 16383, n = r >> 7, k = r & 127;
        int sidx = (l * 128 + k) * 128 + n;
        g_w2t[idx]  = __float2half_rn(mw2[sidx]);
        g_cw2t[idx] = __float2half_rn(cw2[sidx]);
        g_iwt[idx]  = __float2half_rn(iw[sidx]);
        g_cw1t[idx] = __float2half_rn(cw1[sidx]);
    }
    if (idx < NLAYER * 128 * 64) {
        int l = idx >> 13, r = idx & 8191, n = r >> 6, k = r & 63;
        float v = (k < NGAUSS) ? mw1[(l * NGAUSS + k) * 128 + n] : 0.0f;
        g_w1t[idx] = __float2half_rn(v);
    }
    if (idx < 2 * GG) out[2 * NN + idx] = 0.0f;
    {
        int e = idx;
        int s = ei[e], d = ei[EE + e];
        float dx = pos[3*s]   - pos[3*d];
        float dy = pos[3*s+1] - pos[3*d+1];
        float dz = pos[3*s+2] - pos[3*d+2];
        float dist = sqrtf(dx*dx + dy*dy + dz*dz);
        g_dist[e] = dist;
        g_C[e] = 0.5f * (__cosf(dist * (3.14159265358979323846f / 10.0f)) + 1.0f);
        atomicAdd(&g_cnt[d], 1);
    }
    for (int j = idx; j < NN * 32; j += EE)
        ((float4*)g_h)[j] = ((const float4*)emb)[atoms[j >> 5] * 32 + (j & 31)];
}

// ---------------- launch 2: exclusive scan of g_cnt -> g_cur (+ re-zero g_cnt) ----------------
__global__ void __launch_bounds__(1024) k_scan() {
    __shared__ int warp_sums[32];
    __shared__ int s_carry;
    int tid = threadIdx.x;
    if (tid == 0) s_carry = 0;
    __syncthreads();
    for (int base = 0; base < NN; base += 1024) {
        int i = base + tid;
        int v = (i < NN) ? g_cnt[i] : 0;
        int incl = v;
#pragma unroll
        for (int off = 1; off < 32; off <<= 1) {
            int n = __shfl_up_sync(0xffffffff, incl, off);
            if ((tid & 31) >= off) incl += n;
        }
        if ((tid & 31) == 31) warp_sums[tid >> 5] = incl;
        __syncthreads();
        if (tid < 32) {
            int ws = warp_sums[tid];
            int wi = ws;
#pragma unroll
            for (int off = 1; off < 32; off <<= 1) {
                int n = __shfl_up_sync(0xffffffff, wi, off);
                if (tid >= off) wi += n;
            }
            warp_sums[tid] = wi - ws;
        }
        __syncthreads();
        int excl = s_carry + warp_sums[tid >> 5] + incl - v;
        if (i < NN) g_cur[i] = excl;
        __syncthreads();
        if (tid == 1023) s_carry = excl + v;
        __syncthreads();
    }
    for (int i = tid; i < NN; i += 1024) g_cnt[i] = 0;   // reset for next run
}

// ---------------- launch 3: xl = fp16(h) @ cw1[0]  (fp16 mma, node-style) ----------------
#define X_A  0
#define X_B  34816
#define SMEM_XL 69632

__global__ void __launch_bounds__(512, 1) k_xl_mma() {
    extern __shared__ char sp[];
    const u32 sbase = smem_u32(sp);
    int tid = threadIdx.x, lane = tid & 31, wid = tid >> 5;
    int wm = wid & 3, wn = wid >> 2;
    int row0 = blockIdx.x * 128;

    int a_r = (lane & 7) + ((lane >> 3) & 1) * 8;
    int a_k = (lane >> 4) * 8;
    int b_r = (lane & 7) + (lane >> 4) * 8;
    int b_k = ((lane >> 3) & 1) * 8;
    u32 A_b = sbase + X_A + (u32)(wm * 32 + a_r) * 272 + (u32)a_k * 2;
    u32 B_b = sbase + X_B + (u32)(wn * 32 + b_r) * 272 + (u32)b_k * 2;
    int r0base  = wm * 32 + (lane >> 2);
    int colbase = wn * 32 + (lane & 3) * 2;

    for (int i = tid; i < 128 * 32; i += 512) {
        int r = i >> 5, c4 = i & 31;
        int row = row0 + r;
        float4 v = make_float4(0.f, 0.f, 0.f, 0.f);
        if (row < NN) v = *(const float4*)(g_h + (size_t)row * 128 + c4 * 4);
        *(uint2*)(sp + X_A + r * 272 + c4 * 8) = make_uint2(pkh2(v.x, v.y), pkh2(v.z, v.w));
    }
    {
        const uint4* bh = (const uint4*)g_cw1t;   // layer 0
        for (int i = tid; i < 2048; i += 512) {
            int n = i >> 4, ch = i & 15;
            *(uint4*)(sp + X_B + n * 272 + ch * 16) = bh[i];
        }
    }
    __syncthreads();

    float acc[2][4][4];
    ZACC4(acc);
    gemm_1p<8, 272>(acc, A_b, B_b);

#pragma unroll
    for (int mi = 0; mi < 2; mi++) {
        int r0 = r0base + mi * 16;
#pragma unroll
        for (int rr = 0; rr < 2; rr++) {
            int row = row0 + r0 + rr * 8;
            if (row >= NN) continue;
#pragma unroll
            for (int ni = 0; ni < 4; ni++) {
                int c = colbase + ni * 8;
                *(float2*)(g_xl + (size_t)row * 128 + c) =
                    make_float2(acc[mi][ni][2*rr], acc[mi][ni][2*rr + 1]);
            }
        }
    }
}

// ---------------- launch 4: permute edges into dst-sorted order ----------------
__global__ void __launch_bounds__(256) k_permute(const int* __restrict__ ei) {
    int e = blockIdx.x * 256 + threadIdx.x;
    if (e >= EE) return;
    int d = ei[EE + e];
    int pos = atomicAdd(&g_cur[d], 1);
    g_sd[pos]  = g_dist[e];
    g_sc[pos]  = g_C[e];
    g_ss[pos]  = ei[e];
    g_sdt[pos] = d;
}

// ---------------- edge pipeline: EXACT R9 champion structure ----------------
#define O_A1  0
#define O_B1  18432
#define O_A2  36864            // stride 272B
#define O_B2  71680
#define O_MSG 106496           // 128 rows x 512B (fp32 msg)
#define O_SB1 172032
#define O_SB2 172544
#define O_SCT 173056           // [2][128] f32
#define O_SRC 174080           // [2][128] i32
#define O_SDST 175104          // [2][128] i32
#define SMEM_EDGE 176128

// windowed gaussian row fill: values with |d-g*sp| > 6.5*sp round to 0 in fp16
__device__ __forceinline__ void ea_row_fill(char* rowH, float dv) {
    const float spc = 10.0f / 49.0f;
    const float coeff = -0.5f / (spc * spc);
#pragma unroll
    for (int q = 0; q < 8; q++) *(uint4*)(rowH + q * 16) = make_uint4(0, 0, 0, 0);
    float gf = dv * (49.0f / 10.0f);
    int gbeg = (int)(gf - 6.5f) + 1;
    if (gbeg < 0) gbeg = 0;
    int gend = (int)(gf + 6.5f);
    if (gend > NGAUSS - 1) gend = NGAUSS - 1;
    for (int g = gbeg; g <= gend; g++) {
        float t = dv - (float)g * spc;
        *(__half*)(rowH + g * 2) = __float2half_rn(__expf(coeff * t * t));
    }
}

__global__ void __launch_bounds__(512, 1) k_edge_mma(
        int layer, const float* __restrict__ b1, const float* __restrict__ b2) {
    extern __shared__ char sp[];
    const u32 sbase = smem_u32(sp);
    int tid = threadIdx.x, lane = tid & 31, wid = tid >> 5;   // wid 0..15
    int wm = wid & 3, wn = wid >> 2;

    float* sb1f = (float*)(sp + O_SB1);
    float* sb2f = (float*)(sp + O_SB2);
    float* sct  = (float*)(sp + O_SCT);
    int*   ssrc = (int*)(sp + O_SRC);
    int*   sdst = (int*)(sp + O_SDST);

    // ---- weights to SMEM (once per launch) ----
    {
        const uint4* w1 = (const uint4*)(g_w1t + layer * 8192);
        for (int i = tid; i < 1024; i += 512) {
            int n = i >> 3, ch = i & 7;
            *(uint4*)(sp + O_B1 + n * 144 + ch * 16) = w1[i];
        }
        const uint4* w2 = (const uint4*)(g_w2t + layer * 16384);
        for (int i = tid; i < 2048; i += 512) {
            int n = i >> 4, ch = i & 15;
            *(uint4*)(sp + O_B2 + n * 272 + ch * 16) = w2[i];
        }
        if (tid < 128) { sb1f[tid] = b1[tid]; sb2f[tid] = b2[tid]; }
    }

    int a_r = (lane & 7) + ((lane >> 3) & 1) * 8;
    int a_k = (lane >> 4) * 8;
    int b_r = (lane & 7) + (lane >> 4) * 8;
    int b_k = ((lane >> 3) & 1) * 8;

    u32 A1_b = sbase + O_A1 + (u32)(wm * 32 + a_r) * 144 + (u32)a_k * 2;
    u32 B1_b = sbase + O_B1 + (u32)(wn * 32 + b_r) * 144 + (u32)b_k * 2;
    u32 A2_b = sbase + O_A2 + (u32)(wm * 32 + a_r) * 272 + (u32)a_k * 2;
    u32 B2_b = sbase + O_B2 + (u32)(wn * 32 + b_r) * 272 + (u32)b_k * 2;

    int r0base  = wm * 32 + (lane >> 2);
    int colbase = wn * 32 + (lane & 3) * 2;

    // ---- prologue: EA + meta for first tile ----
    if (tid < 128) {
        int e0 = blockIdx.x * 128;
        ea_row_fill(sp + O_A1 + tid * 144, g_sd[e0 + tid]);
        ssrc[tid] = g_ss[e0 + tid];
        sdst[tid] = g_sdt[e0 + tid];
        sct[tid]  = g_sc[e0 + tid];
    }
    __syncthreads();

    int pb = 0;
    for (int t = blockIdx.x; t < NTILES; t += EGRID, pb ^= 1) {
        float acc[2][4][4];
        ZACC4(acc);
        gemm_1p<4, 144>(acc, A1_b, B1_b);
        epi_ssp_h(acc, sb1f, sp + O_A2, r0base, colbase);
        __syncthreads();   // [A] A2 visible for GEMM2; A1 free for next EA

        int nt = t + EGRID;
        bool hasnext = nt < NTILES;
        float dv = 0.f, pm_c = 0.f;
        int pm_s = 0, pm_d = 0;
        if (hasnext && tid < 128) {
            dv   = g_sd[nt * 128 + tid];
            pm_s = g_ss[nt * 128 + tid];
            pm_d = g_sdt[nt * 128 + tid];
            pm_c = g_sc[nt * 128 + tid];
        }

        ZACC4(acc);
        gemm_1p<8, 272>(acc, A2_b, B2_b);

        if (hasnext && tid < 128) {
            ea_row_fill(sp + O_A1 + tid * 144, dv);
            int nb = (pb ^ 1) * 128;
            ssrc[nb + tid] = pm_s; sdst[nb + tid] = pm_d; sct[nb + tid] = pm_c;
        }
        __syncthreads();   // [B] GEMM2 A2-reads done; EA/meta visible for next iter

        // ---- epi2: msg = (acc+b2)*C -> fp32 into own MSG bytes ----
        const float* sctp = sct + pb * 128;
#pragma unroll
        for (int mi = 0; mi < 2; mi++) {
#pragma unroll
            for (int rr = 0; rr < 2; rr++) {
                int rt = r0base + mi * 16 + rr * 8;
                float ct = sctp[rt];
#pragma unroll
                for (int ni = 0; ni < 4; ni++) {
                    int cg = colbase + ni * 8;
                    float v0 = (acc[mi][ni][2*rr]     + sb2f[cg])     * ct;
                    float v1 = (acc[mi][ni][2*rr + 1] + sb2f[cg + 1]) * ct;
                    *(float2*)(sp + O_MSG + (u32)rt * 512 + (u32)cg * 4) = make_float2(v0, v1);
                }
            }
        }
        __syncwarp();

        // ---- scatter own 32 rows x 32 cols; overlaps next GEMM1 (no barrier after) ----
        {
            const int* sso = ssrc + pb * 128;
            const int* sdo = sdst + pb * 128;
            int grp = lane >> 3, chunk = lane & 7;
            int rbeg = wm * 32 + grp * 8;
            u32 moff = (u32)O_MSG + (u32)(wn * 128) + (u32)(chunk * 16);
            int coff = wn * 32 + chunk * 4;
            float4 a4 = make_float4(0.f, 0.f, 0.f, 0.f);
            int cur = sdo[rbeg];
#pragma unroll
            for (int p4 = 0; p4 < 2; p4++) {
                int r0 = rbeg + p4 * 4;
                int sr[4], sd[4];
#pragma unroll
                for (int j = 0; j < 4; j++) { sr[j] = sso[r0 + j]; sd[j] = sdo[r0 + j]; }
                float4 x[4];
#pragma unroll
                for (int j = 0; j < 4; j++)
                    x[j] = *(const float4*)(g_xl + (size_t)sr[j] * 128 + coff);
#pragma unroll
                for (int j = 0; j < 4; j++) {
                    if (sd[j] != cur) {
                        red4(g_agg + (size_t)cur * 128 + coff, a4.x, a4.y, a4.z, a4.w);
                        a4 = make_float4(0.f, 0.f, 0.f, 0.f);
                        cur = sd[j];
                    }
                    float4 m = *(const float4*)(sp + moff + (u32)(r0 + j) * 512);
                    a4.x += m.x * x[j].x; a4.y += m.y * x[j].y;
                    a4.z += m.z * x[j].z; a4.w += m.w * x[j].w;
                }
            }
            red4(g_agg + (size_t)cur * 128 + coff, a4.x, a4.y, a4.z, a4.w);
        }
    }
}

// ---------------- fused node update: fp16 1-pass, 512 threads ----------------
#define N_A  0
#define N_B  34816
#define SMEM_NODEM 69632

__global__ void __launch_bounds__(512, 1) k_node_mma(
        const float* __restrict__ cb2, const float* __restrict__ ib,
        int layer, int has_next) {
    extern __shared__ char sp[];
    const u32 sbase = smem_u32(sp);
    int tid = threadIdx.x, lane = tid & 31, wid = tid >> 5;
    int wm = wid & 3, wn = wid >> 2;
    int row0 = blockIdx.x * 128;

    int a_r = (lane & 7) + ((lane >> 3) & 1) * 8;
    int a_k = (lane >> 4) * 8;
    int b_r = (lane & 7) + (lane >> 4) * 8;
    int b_k = ((lane >> 3) & 1) * 8;
    u32 A_b = sbase + N_A + (u32)(wm * 32 + a_r) * 272 + (u32)a_k * 2;
    u32 B_b = sbase + N_B + (u32)(wn * 32 + b_r) * 272 + (u32)b_k * 2;
    int r0base  = wm * 32 + (lane >> 2);
    int colbase = wn * 32 + (lane & 3) * 2;

    // ---- A <- fp16(agg); zero agg; B <- cw2 ----
    for (int i = tid; i < 128 * 32; i += 512) {
        int r = i >> 5, c4 = i & 31;
        int row = row0 + r;
        float4 v = make_float4(0.f, 0.f, 0.f, 0.f);
        if (row < NN) {
            float* ap = g_agg + (size_t)row * 128 + c4 * 4;
            v = *(const float4*)ap;
            *(float4*)ap = make_float4(0.f, 0.f, 0.f, 0.f);
        }
        *(uint2*)(sp + N_A + r * 272 + c4 * 8) = make_uint2(pkh2(v.x, v.y), pkh2(v.z, v.w));
    }
    {
        const uint4* bh = (const uint4*)(g_cw2t + layer * 16384);
        for (int i = tid; i < 2048; i += 512) {
            int n = i >> 4, ch = i & 15;
            *(uint4*)(sp + N_B + n * 272 + ch * 16) = bh[i];
        }
    }
    __syncthreads();

    float acc[2][4][4];
    ZACC4(acc);
    gemm_1p<8, 272>(acc, A_b, B_b);
    __syncthreads();

    epi_ssp_h(acc, cb2, sp + N_A, r0base, colbase);
    {
        const uint4* bh = (const uint4*)(g_iwt + layer * 16384);
        for (int i = tid; i < 2048; i += 512) {
            int n = i >> 4, ch = i & 15;
            *(uint4*)(sp + N_B + n * 272 + ch * 16) = bh[i];
        }
    }
    __syncthreads();

    ZACC4(acc);
    gemm_1p<8, 272>(acc, A_b, B_b);
    __syncthreads();

    // ---- epi2: h += acc + ib ; A <- fp16(h_new) ----
#pragma unroll
    for (int mi = 0; mi < 2; mi++) {
        int r0 = r0base + mi * 16;
#pragma unroll
        for (int rr = 0; rr < 2; rr++) {
            int r = r0 + rr * 8;
            int row = row0 + r;
#pragma unroll
            for (int ni = 0; ni < 4; ni++) {
                int c = colbase + ni * 8;
                float v0 = acc[mi][ni][2*rr]     + ib[c];
                float v1 = acc[mi][ni][2*rr + 1] + ib[c + 1];
                float2 hv = make_float2(0.f, 0.f);
                float* hp = g_h + (size_t)row * 128 + c;
                if (row < NN) hv = *(const float2*)hp;
                hv.x += v0; hv.y += v1;
                if (row < NN) *(float2*)hp = hv;
                *(u32*)(sp + N_A + r * 272 + c * 2) = pkh2(hv.x, hv.y);
            }
        }
    }
    if (has_next) {
        const uint4* bh = (const uint4*)(g_cw1t + (layer + 1) * 16384);
        for (int i = tid; i < 2048; i += 512) {
            int n = i >> 4, ch = i & 15;
            *(uint4*)(sp + N_B + n * 272 + ch * 16) = bh[i];
        }
        __syncthreads();

        ZACC4(acc);
        gemm_1p<8, 272>(acc, A_b, B_b);

#pragma unroll
        for (int mi = 0; mi < 2; mi++) {
            int r0 = r0base + mi * 16;
#pragma unroll
            for (int rr = 0; rr < 2; rr++) {
                int row = row0 + r0 + rr * 8;
                if (row >= NN) continue;
#pragma unroll
                for (int ni = 0; ni < 4; ni++) {
                    int c = colbase + ni * 8;
                    *(float2*)(g_xl + (size_t)row * 128 + c) =
                        make_float2(acc[mi][ni][2*rr], acc[mi][ni][2*rr + 1]);
                }
            }
        }
    }
}

// ---------------- readout ----------------
__global__ void __launch_bounds__(128) k_read(const int* __restrict__ batch,
        const float* __restrict__ lw, const float* __restrict__ lb,
        const float* __restrict__ ew, const float* __restrict__ ebp,
        const float* __restrict__ qw, const float* __restrict__ qbp,
        float* __restrict__ out) {
    extern __shared__ float sm[];
    float* Hs  = sm;
    float* Ws  = Hs + 128 * 129;
    float* sb  = Ws + 128 * 64;
    float* sew = sb + 64;
    float* sqw = sew + 64;
    int tid = threadIdx.x;
    int row0 = blockIdx.x * 128;
    for (int i = tid; i < 128 * 128; i += 128) {
        int r = i >> 7, c = i & 127;
        int row = row0 + r;
        Hs[r * 129 + c] = (row < NN) ? g_h[(size_t)row * 128 + c] : 0.f;
    }
    for (int i = tid; i < 128 * 64; i += 128) Ws[i] = lw[i];
    if (tid < 64) { sb[tid] = lb[tid]; sew[tid] = ew[tid]; sqw[tid] = qw[tid]; }
    __syncthreads();
    int row = row0 + tid;
    if (row >= NN) return;
    float e = ebp[0], q = qbp[0];
    const float* hr = Hs + tid * 129;
#pragma unroll 2
    for (int j = 0; j < 64; j++) {
        float a = sb[j];
#pragma unroll 8
        for (int k = 0; k < 128; k++) a += hr[k] * Ws[k * 64 + j];
        float hh = ssp(a);
        e += hh * sew[j];
        q += hh * sqw[j];
    }
    out[row] = e;
    out[NN + row] = q;
    int b = batch[row];
    atomicAdd(out + 2 * NN + b, e);
    atomicAdd(out + 2 * NN + GG + b, q);
}

// ---------------- host ----------------
extern "C" void kernel_launch(void* const* d_in, const int* in_sizes, int n_in,
                              void* d_out, int out_size) {
    const int*   atoms = (const int*)d_in[0];
    const float* pos   = (const float*)d_in[1];
    const int*   batch = (const int*)d_in[2];
    const int*   ei    = (const int*)d_in[3];
    const float* emb   = (const float*)d_in[4];
    const float* mw1   = (const float*)d_in[5];
    const float* mb1   = (const float*)d_in[6];
    const float* mw2   = (const float*)d_in[7];
    const float* mb2   = (const float*)d_in[8];
    const float* cw1   = (const float*)d_in[9];
    const float* cw2   = (const float*)d_in[10];
    const float* cb2   = (const float*)d_in[11];
    const float* iw    = (const float*)d_in[12];
    const float* ib    = (const float*)d_in[13];
    const float* l1w   = (const float*)d_in[14];
    const float* l1b   = (const float*)d_in[15];
    const float* ew    = (const float*)d_in[16];
    const float* eb    = (const float*)d_in[17];
    const float* qw    = (const float*)d_in[18];
    const float* qb    = (const float*)d_in[19];
    float* out = (float*)d_out;

    constexpr int SMEM_READ = (128 * 129 + 128 * 64 + 192) * 4;

    cudaFuncSetAttribute(k_xl_mma,   cudaFuncAttributeMaxDynamicSharedMemorySize, SMEM_XL);
    cudaFuncSetAttribute(k_edge_mma, cudaFuncAttributeMaxDynamicSharedMemorySize, SMEM_EDGE);
    cudaFuncSetAttribute(k_node_mma, cudaFuncAttributeMaxDynamicSharedMemorySize, SMEM_NODEM);
    cudaFuncSetAttribute(k_read,     cudaFuncAttributeMaxDynamicSharedMemorySize, SMEM_READ);

    const int NODE_BLOCKS = (NN + 127) / 128;   // 391

    k_prep_init<<<EE / 256, 256>>>(pos, ei, atoms, emb, mw1, mw2, cw2, iw, cw1, out);
    k_scan<<<1, 1024>>>();
    k_xl_mma<<<NODE_BLOCKS, 512, SMEM_XL>>>();
    k_permute<<<EE / 256, 256>>>(ei);

    for (int l = 0; l < NLAYER; l++) {
        k_edge_mma<<<EGRID, 512, SMEM_EDGE>>>(l, mb1 + (size_t)l * FF, mb2 + (size_t)l * FF);
        k_node_mma<<<NODE_BLOCKS, 512, SMEM_NODEM>>>(cb2 + (size_t)l * HH, ib + (size_t)l * HH,
                                                     l, (l < NLAYER - 1) ? 1 : 0);
    }
    k_read<<<NODE_BLOCKS, 128, SMEM_READ>>>(batch, l1w, l1b, ew, eb, qw, qb, out);
}